// round 2
// baseline (speedup 1.0000x reference)
#include <cuda_runtime.h>
#include <cstdint>

// Problem constants: B=131072, T=40, H=40, C=4
#define TT 40
#define HH 40
#define UPT 10          // hidden units per thread (4 threads per sequence)
#define SEQ_PER_CTA 32  // blockDim 128 / 4

typedef unsigned long long ull;

// ---- packed fp32x2 helpers (sm_103a: FFMA2 only reachable via PTX) ----
__device__ __forceinline__ ull ffma2(ull a, ull b, ull c) {
    ull d;
    asm("fma.rn.f32x2 %0, %1, %2, %3;" : "=l"(d) : "l"(a), "l"(b), "l"(c));
    return d;
}
__device__ __forceinline__ ull pack2(float lo, float hi) {
    ull r;
    asm("mov.b64 %0, {%1, %2};" : "=l"(r) : "f"(lo), "f"(hi));
    return r;
}
__device__ __forceinline__ void unpack2(ull v, float& lo, float& hi) {
    asm("mov.b64 {%0, %1}, %2;" : "=f"(lo), "=f"(hi) : "l"(v));
}
__device__ __forceinline__ ull pack_bits(float lo, float hi) {
    return (ull)__float_as_uint(lo) | ((ull)__float_as_uint(hi) << 32);
}

// ---- fast-accurate activations (~1e-7 rel err; MUFU.TANH too coarse for argmax) ----
__device__ __forceinline__ float ex2f(float x) {
    float r; asm("ex2.approx.f32 %0, %1;" : "=f"(r) : "f"(x)); return r;
}
__device__ __forceinline__ float rcpf(float x) {
    float r; asm("rcp.approx.f32 %0, %1;" : "=f"(r) : "f"(x)); return r;
}
__device__ __forceinline__ float sigf(float x) {
    return rcpf(1.0f + ex2f(x * -1.4426950408889634f));
}
__device__ __forceinline__ float tanhfast(float x) {
    return fmaf(-2.0f, rcpf(1.0f + ex2f(x * 2.8853900817779268f)), 1.0f);
}

__global__ __launch_bounds__(128)
void lstm_fused_kernel(const float* __restrict__ x,
                       const float* __restrict__ W_ih,
                       const float* __restrict__ W_hh,
                       const float* __restrict__ b_ih,
                       const float* __restrict__ b_hh,
                       const float* __restrict__ W_fc,
                       const float* __restrict__ b_fc,
                       float* __restrict__ out,
                       int B, int out_size)
{
    // Packed weights: sWif[k][u] = (W_hh[u][k], W_hh[40+u][k]),
    //                 sWgo[k][u] = (W_hh[80+u][k], W_hh[120+u][k]).
    __shared__ __align__(16) ull sWif[HH * HH];   // 12.8 KB
    __shared__ __align__(16) ull sWgo[HH * HH];   // 12.8 KB
    __shared__ __align__(16) ull sBif[HH], sBgo[HH], sWinIf[HH], sWinGo[HH];
    __shared__ float sWfc[4 * HH];
    __shared__ float sbfc[4];
    __shared__ float sx[TT * SEQ_PER_CTA];        // staged x, layout [t][seq]

    const int tid = threadIdx.x;

    for (int idx = tid; idx < HH * HH; idx += blockDim.x) {
        int k = idx / HH, u = idx % HH;
        sWif[k * HH + u] = pack_bits(W_hh[u * HH + k],          W_hh[(HH + u) * HH + k]);
        sWgo[k * HH + u] = pack_bits(W_hh[(2*HH + u) * HH + k], W_hh[(3*HH + u) * HH + k]);
    }
    for (int u = tid; u < HH; u += blockDim.x) {
        sBif[u]   = pack_bits(b_ih[u]        + b_hh[u],        b_ih[HH + u]   + b_hh[HH + u]);
        sBgo[u]   = pack_bits(b_ih[2*HH + u] + b_hh[2*HH + u], b_ih[3*HH + u] + b_hh[3*HH + u]);
        sWinIf[u] = pack_bits(W_ih[u],        W_ih[HH + u]);
        sWinGo[u] = pack_bits(W_ih[2*HH + u], W_ih[3*HH + u]);
    }
    for (int i = tid; i < 4 * HH; i += blockDim.x) sWfc[i] = W_fc[i];
    if (tid < 4) sbfc[tid] = b_fc[tid];

    // Stage this CTA's x (coalesced global reads)
    const int seq_base = blockIdx.x * SEQ_PER_CTA;
    for (int idx = tid; idx < SEQ_PER_CTA * TT; idx += blockDim.x) {
        int sq = idx / TT, t = idx % TT;
        sx[t * SEQ_PER_CTA + sq] = x[(size_t)(seq_base + sq) * TT + t];
    }
    __syncthreads();

    const int sub = tid & 3;          // which quarter of the hidden state this thread owns
    const int sq  = tid >> 2;         // sequence within CTA
    const int b   = seq_base + sq;
    const int u0  = sub * UPT;
    const bool active = (b < B);

    const ull* __restrict__ wifp = sWif + u0;
    const ull* __restrict__ wgop = sWgo + u0;

    float h_own[UPT], c[UPT];
#pragma unroll
    for (int j = 0; j < UPT; j++) { h_own[j] = 0.0f; c[j] = 0.0f; }

    for (int t = 0; t < TT; t++) {
        const float xt = sx[t * SEQ_PER_CTA + sq];
        const ull xt2 = pack2(xt, xt);

        ull aif[UPT], ago[UPT];
#pragma unroll
        for (int j = 0; j < UPT; j++) {
            aif[j] = ffma2(xt2, sWinIf[u0 + j], sBif[u0 + j]);
            ago[j] = ffma2(xt2, sWinGo[u0 + j], sBgo[u0 + j]);
        }

#pragma unroll
        for (int k = 0; k < HH; k++) {
            const float hk = __shfl_sync(0xffffffffu, h_own[k % UPT], k / UPT, 4);
            const ull hk2 = pack2(hk, hk);
            const ull* __restrict__ wif = wifp + k * HH;
            const ull* __restrict__ wgo = wgop + k * HH;
#pragma unroll
            for (int j = 0; j < UPT; j++) {
                aif[j] = ffma2(hk2, wif[j], aif[j]);
                ago[j] = ffma2(hk2, wgo[j], ago[j]);
            }
        }

#pragma unroll
        for (int j = 0; j < UPT; j++) {
            float ig, fg, gg, og;
            unpack2(aif[j], ig, fg);
            unpack2(ago[j], gg, og);
            const float iv = sigf(ig);
            const float fv = sigf(fg);
            const float gv = tanhfast(gg);
            const float ov = sigf(og);
            // mirror jax rounding: c_new = rn(rn(f*c) + rn(i*g)) (no contraction)
            const float cn = __fadd_rn(__fmul_rn(fv, c[j]), __fmul_rn(iv, gv));
            c[j]     = cn;
            h_own[j] = __fmul_rn(ov, tanhfast(cn));
        }
        // warp-synchronous: shuffles at the top of next step see updated h_own
    }

    // FC head: partial dot per thread, butterfly-reduce across the 4-lane group
    float lg[4];
#pragma unroll
    for (int cc = 0; cc < 4; cc++) {
        float s = 0.0f;
#pragma unroll
        for (int j = 0; j < UPT; j++) s = fmaf(h_own[j], sWfc[cc * HH + u0 + j], s);
        lg[cc] = s;
    }
#pragma unroll
    for (int cc = 0; cc < 4; cc++) {
        lg[cc] += __shfl_xor_sync(0xffffffffu, lg[cc], 1, 4);
        lg[cc] += __shfl_xor_sync(0xffffffffu, lg[cc], 2, 4);
        lg[cc] = __fadd_rn(lg[cc], sbfc[cc]);
    }

    if (active && sub == 0) {
        reinterpret_cast<float4*>(out)[b] = make_float4(lg[0], lg[1], lg[2], lg[3]);
        if (out_size >= 5 * B) {
            float best = lg[0];
            int   bi   = 0;
#pragma unroll
            for (int cc = 1; cc < 4; cc++) {
                if (lg[cc] > best) { best = lg[cc]; bi = cc; }  // strict >: first max (jnp semantics)
            }
            out[(size_t)4 * B + b] = (float)bi;
        }
    }
}

extern "C" void kernel_launch(void* const* d_in, const int* in_sizes, int n_in,
                              void* d_out, int out_size)
{
    const float* x    = (const float*)d_in[0];
    const float* W_ih = (const float*)d_in[1];
    const float* W_hh = (const float*)d_in[2];
    const float* b_ih = (const float*)d_in[3];
    const float* b_hh = (const float*)d_in[4];
    const float* W_fc = (const float*)d_in[5];
    const float* b_fc = (const float*)d_in[6];

    const int B = in_sizes[0] / TT;
    const int threads = 128;
    const int blocks  = (B + SEQ_PER_CTA - 1) / SEQ_PER_CTA;

    lstm_fused_kernel<<<blocks, threads>>>(x, W_ih, W_hh, b_ih, b_hh,
                                           W_fc, b_fc, (float*)d_out, B, out_size);
}

// round 3
// speedup vs baseline: 2.2335x; 2.2335x over previous
#include <cuda_runtime.h>
#include <cstdint>

// Problem constants: B=131072, T=40, H=40, C=4
#define TT   40
#define HH   40
#define UPT  5            // hidden units per lane (8 subs cover H=40)
#define NSEQ 4            // sequences per lane (register reuse factor for weights)
#define SEQ_PER_WARP 16   // 4 groups * NSEQ
#define SEQ_PER_CTA  64   // 4 warps

typedef unsigned long long ull;

// ---- packed fp32x2 helpers (sm_103a: FFMA2 only via PTX) ----
__device__ __forceinline__ ull ffma2(ull a, ull b, ull c) {
    ull d;
    asm("fma.rn.f32x2 %0, %1, %2, %3;" : "=l"(d) : "l"(a), "l"(b), "l"(c));
    return d;
}
__device__ __forceinline__ ull pack2(float lo, float hi) {
    ull r;
    asm("mov.b64 %0, {%1, %2};" : "=l"(r) : "f"(lo), "f"(hi));
    return r;
}
__device__ __forceinline__ void unpack2(ull v, float& lo, float& hi) {
    asm("mov.b64 {%0, %1}, %2;" : "=f"(lo), "=f"(hi) : "l"(v));
}
__device__ __forceinline__ ull pack_bits(float lo, float hi) {
    return (ull)__float_as_uint(lo) | ((ull)__float_as_uint(hi) << 32);
}

// ---- fast-accurate activations (~1e-7 rel err; MUFU.TANH too coarse for argmax) ----
__device__ __forceinline__ float ex2f(float x) {
    float r; asm("ex2.approx.f32 %0, %1;" : "=f"(r) : "f"(x)); return r;
}
__device__ __forceinline__ float rcpf(float x) {
    float r; asm("rcp.approx.f32 %0, %1;" : "=f"(r) : "f"(x)); return r;
}
__device__ __forceinline__ float sigf(float x) {
    return rcpf(1.0f + ex2f(x * -1.4426950408889634f));
}
__device__ __forceinline__ float tanhfast(float x) {
    return fmaf(-2.0f, rcpf(1.0f + ex2f(x * 2.8853900817779268f)), 1.0f);
}

// Weight row layout per (sub, k): 12 ull slots, [0..4]=(i,f) pairs, [6..10]=(g,o) pairs.
// Per-sub stride 482 ull (= 40*12 + 2): the +2 (16B) stagger puts the 8 subs'
// rows on distinct 16B bank groups (stride 3856 % 128 = 16), avoiding 8-way
// conflicts on the LDS.128 wavefronts.
#define WROW 12
#define SUBSTRIDE 482

__global__ __launch_bounds__(128)
void lstm_fused_kernel(const float* __restrict__ x,
                       const float* __restrict__ W_ih,
                       const float* __restrict__ W_hh,
                       const float* __restrict__ b_ih,
                       const float* __restrict__ b_hh,
                       const float* __restrict__ W_fc,
                       const float* __restrict__ b_fc,
                       float* __restrict__ out,
                       int B, int out_size)
{
    __shared__ __align__(16) ull sW[8 * SUBSTRIDE];           // 30.8 KB
    __shared__ __align__(16) ull sBif[HH], sBgo[HH], sWinIf[HH], sWinGo[HH];
    __shared__ float sWfc[4 * HH];
    __shared__ float sbfc[4];
    __shared__ float sx[SEQ_PER_CTA * (TT + 1)];              // padded rows (bank spread)

    const int tid = threadIdx.x;
    const int seq_base = blockIdx.x * SEQ_PER_CTA;

    // ---- fill packed weights ----
    for (int idx = tid; idx < HH * HH; idx += blockDim.x) {
        int k = idx / HH, u = idx % HH;
        int sub = u / UPT, j = u % UPT;
        ull* row = &sW[sub * SUBSTRIDE + k * WROW];
        row[j]     = pack_bits(W_hh[u * HH + k],          W_hh[(HH + u) * HH + k]);
        row[6 + j] = pack_bits(W_hh[(2*HH + u) * HH + k], W_hh[(3*HH + u) * HH + k]);
    }
    for (int u = tid; u < HH; u += blockDim.x) {
        sBif[u]   = pack_bits(b_ih[u]        + b_hh[u],        b_ih[HH + u]   + b_hh[HH + u]);
        sBgo[u]   = pack_bits(b_ih[2*HH + u] + b_hh[2*HH + u], b_ih[3*HH + u] + b_hh[3*HH + u]);
        sWinIf[u] = pack_bits(W_ih[u],        W_ih[HH + u]);
        sWinGo[u] = pack_bits(W_ih[2*HH + u], W_ih[3*HH + u]);
    }
    for (int i = tid; i < 4 * HH; i += blockDim.x) sWfc[i] = W_fc[i];
    if (tid < 4) sbfc[tid] = b_fc[tid];

    // ---- stage x (coalesced) ----
    for (int idx = tid; idx < SEQ_PER_CTA * TT; idx += blockDim.x) {
        int sq = idx / TT, t = idx % TT;
        int gb = seq_base + sq;
        sx[sq * (TT + 1) + t] = (gb < B) ? x[(size_t)gb * TT + t] : 0.0f;
    }
    __syncthreads();

    const int lane = tid & 31;
    const int w    = tid >> 5;          // warp in CTA
    const int sub  = lane & 7;          // unit slice: [sub*5, sub*5+5)
    const int grp  = lane >> 3;         // sequence group within warp
    const int u0   = sub * UPT;
    // this lane's sequences (within CTA): w*16 + grp*4 + s
    const int sq0  = w * SEQ_PER_WARP + grp * NSEQ;

    const char* __restrict__ wbase = (const char*)&sW[sub * SUBSTRIDE];

    float h[NSEQ][UPT], c[NSEQ][UPT];
#pragma unroll
    for (int s = 0; s < NSEQ; s++)
#pragma unroll
        for (int j = 0; j < UPT; j++) { h[s][j] = 0.0f; c[s][j] = 0.0f; }

    for (int t = 0; t < TT; t++) {
        ull xt2[NSEQ];
#pragma unroll
        for (int s = 0; s < NSEQ; s++) {
            float xv = sx[(sq0 + s) * (TT + 1) + t];
            xt2[s] = pack2(xv, xv);
        }

        ull aif[NSEQ][UPT], ago[NSEQ][UPT];
#pragma unroll
        for (int j = 0; j < UPT; j++) {
            const ull wi = sWinIf[u0 + j], bi = sBif[u0 + j];
            const ull wg = sWinGo[u0 + j], bg = sBgo[u0 + j];
#pragma unroll
            for (int s = 0; s < NSEQ; s++) {
                aif[s][j] = ffma2(xt2[s], wi, bi);
                ago[s][j] = ffma2(xt2[s], wg, bg);
            }
        }

        // k-loop in chunks of 5 (unit ownership granularity). Shuffles for the
        // whole chunk are hoisted to bury the ~26cyc SHFL latency under FMAs.
        for (int m = 0; m < 8; m++) {
            float hk[UPT][NSEQ];
#pragma unroll
            for (int kk = 0; kk < UPT; kk++)
#pragma unroll
                for (int s = 0; s < NSEQ; s++)
                    hk[kk][s] = __shfl_sync(0xffffffffu, h[s][kk], m, 8);

            const char* base = wbase + (size_t)m * (UPT * WROW * 8);
#pragma unroll
            for (int kk = 0; kk < UPT; kk++) {
                const char* row = base + kk * (WROW * 8);
                const ulonglong2 w01 = *reinterpret_cast<const ulonglong2*>(row);
                const ulonglong2 w23 = *reinterpret_cast<const ulonglong2*>(row + 16);
                const ull        w4  = *reinterpret_cast<const ull*>(row + 32);
                const ulonglong2 g01 = *reinterpret_cast<const ulonglong2*>(row + 48);
                const ulonglong2 g23 = *reinterpret_cast<const ulonglong2*>(row + 64);
                const ull        g4  = *reinterpret_cast<const ull*>(row + 80);
#pragma unroll
                for (int s = 0; s < NSEQ; s++) {
                    const ull hk2 = pack2(hk[kk][s], hk[kk][s]);
                    aif[s][0] = ffma2(hk2, w01.x, aif[s][0]);
                    aif[s][1] = ffma2(hk2, w01.y, aif[s][1]);
                    aif[s][2] = ffma2(hk2, w23.x, aif[s][2]);
                    aif[s][3] = ffma2(hk2, w23.y, aif[s][3]);
                    aif[s][4] = ffma2(hk2, w4,    aif[s][4]);
                    ago[s][0] = ffma2(hk2, g01.x, ago[s][0]);
                    ago[s][1] = ffma2(hk2, g01.y, ago[s][1]);
                    ago[s][2] = ffma2(hk2, g23.x, ago[s][2]);
                    ago[s][3] = ffma2(hk2, g23.y, ago[s][3]);
                    ago[s][4] = ffma2(hk2, g4,    ago[s][4]);
                }
            }
        }

        // activations + state update
#pragma unroll
        for (int s = 0; s < NSEQ; s++) {
#pragma unroll
            for (int j = 0; j < UPT; j++) {
                float ig, fg, gg, og;
                unpack2(aif[s][j], ig, fg);
                unpack2(ago[s][j], gg, og);
                const float iv = sigf(ig);
                const float fv = sigf(fg);
                const float gv = tanhfast(gg);
                const float ov = sigf(og);
                // mirror jax rounding: c_new = rn(rn(f*c) + rn(i*g))
                const float cn = __fadd_rn(__fmul_rn(fv, c[s][j]), __fmul_rn(iv, gv));
                c[s][j] = cn;
                h[s][j] = __fmul_rn(ov, tanhfast(cn));
            }
        }
        // warp-synchronous: next step's shuffles (full-mask) see updated h
    }

    // ---- FC head: per-lane partials, xor-reduce over the 8-lane sub group ----
    float lg[NSEQ][4];
#pragma unroll
    for (int s = 0; s < NSEQ; s++) {
#pragma unroll
        for (int cc = 0; cc < 4; cc++) {
            float p = 0.0f;
#pragma unroll
            for (int j = 0; j < UPT; j++) p = fmaf(h[s][j], sWfc[cc * HH + u0 + j], p);
            p += __shfl_xor_sync(0xffffffffu, p, 1, 8);
            p += __shfl_xor_sync(0xffffffffu, p, 2, 8);
            p += __shfl_xor_sync(0xffffffffu, p, 4, 8);
            lg[s][cc] = __fadd_rn(p, sbfc[cc]);
        }
    }

    if (sub == 0) {
#pragma unroll
        for (int s = 0; s < NSEQ; s++) {
            const int b = seq_base + sq0 + s;
            if (b < B) {
                reinterpret_cast<float4*>(out)[b] =
                    make_float4(lg[s][0], lg[s][1], lg[s][2], lg[s][3]);
                if (out_size >= 5 * B) {
                    float best = lg[s][0];
                    int   bi   = 0;
#pragma unroll
                    for (int cc = 1; cc < 4; cc++) {
                        if (lg[s][cc] > best) { best = lg[s][cc]; bi = cc; }
                    }
                    out[(size_t)4 * B + b] = (float)bi;
                }
            }
        }
    }
}

extern "C" void kernel_launch(void* const* d_in, const int* in_sizes, int n_in,
                              void* d_out, int out_size)
{
    const float* x    = (const float*)d_in[0];
    const float* W_ih = (const float*)d_in[1];
    const float* W_hh = (const float*)d_in[2];
    const float* b_ih = (const float*)d_in[3];
    const float* b_hh = (const float*)d_in[4];
    const float* W_fc = (const float*)d_in[5];
    const float* b_fc = (const float*)d_in[6];

    const int B = in_sizes[0] / TT;
    const int threads = 128;
    const int blocks  = (B + SEQ_PER_CTA - 1) / SEQ_PER_CTA;

    lstm_fused_kernel<<<blocks, threads>>>(x, W_ih, W_hh, b_ih, b_hh,
                                           W_fc, b_fc, (float*)d_out, B, out_size);
}